// round 1
// baseline (speedup 1.0000x reference)
#include <cuda_runtime.h>
#include <math.h>

#define B_   2
#define T_   2048
#define D_   512
#define H_   8
#define HD_  64
#define QKV3 (3 * D_)   // 1536
#define NROW (B_ * T_)  // 4096

// Scratch (no cudaMalloc allowed)
__device__ float g_qkv[B_ * T_ * QKV3];   // (B,T, [q|k|v] each D)  ~25 MB
__device__ float g_attn[B_ * T_ * D_];    // (B,T,D) attention output ~8 MB

// ---------------------------------------------------------------------------
// C[n,m] = sum_k A[n,k] * W[m,k] + bias[m]
// A: (N,K) row-major, W: (M,K) row-major. N,M multiples of 128, K multiple of 8.
// 128x128 block tile, BK=8, 256 threads, 8x8 micro-tile per thread.
// ---------------------------------------------------------------------------
__global__ __launch_bounds__(256)
void gemm_tn_bias(const float* __restrict__ A, const float* __restrict__ W,
                  const float* __restrict__ bias, float* __restrict__ C,
                  int N, int M, int K)
{
    __shared__ float As[8][128];
    __shared__ float Ws[8][128];

    const int tid = threadIdx.x;
    const int n0 = blockIdx.y * 128;
    const int m0 = blockIdx.x * 128;

    // loader: each thread fetches one float4 from A and one from W per K-tile
    const int lr = tid >> 1;          // 0..127 (row within tile)
    const int lc = (tid & 1) * 4;     // 0 or 4 (k offset)
    const float* Aptr = A + (size_t)(n0 + lr) * K + lc;
    const float* Wptr = W + (size_t)(m0 + lr) * K + lc;

    const int tx = tid & 15;          // 0..15 -> output cols
    const int ty = tid >> 4;          // 0..15 -> output rows

    float c[8][8];
#pragma unroll
    for (int i = 0; i < 8; i++)
#pragma unroll
        for (int j = 0; j < 8; j++) c[i][j] = 0.f;

    for (int k0 = 0; k0 < K; k0 += 8) {
        float4 a4 = *(const float4*)(Aptr + k0);
        float4 w4 = *(const float4*)(Wptr + k0);
        __syncthreads();
        As[lc + 0][lr] = a4.x; As[lc + 1][lr] = a4.y;
        As[lc + 2][lr] = a4.z; As[lc + 3][lr] = a4.w;
        Ws[lc + 0][lr] = w4.x; Ws[lc + 1][lr] = w4.y;
        Ws[lc + 2][lr] = w4.z; Ws[lc + 3][lr] = w4.w;
        __syncthreads();

#pragma unroll
        for (int kk = 0; kk < 8; kk++) {
            float a[8], b[8];
            *(float4*)&a[0] = *(const float4*)&As[kk][ty * 4];
            *(float4*)&a[4] = *(const float4*)&As[kk][64 + ty * 4];
            *(float4*)&b[0] = *(const float4*)&Ws[kk][tx * 4];
            *(float4*)&b[4] = *(const float4*)&Ws[kk][64 + tx * 4];
#pragma unroll
            for (int i = 0; i < 8; i++)
#pragma unroll
                for (int j = 0; j < 8; j++)
                    c[i][j] = fmaf(a[i], b[j], c[i][j]);
        }
    }

#pragma unroll
    for (int i = 0; i < 8; i++) {
        int n = n0 + ((i < 4) ? (ty * 4 + i) : (64 + ty * 4 + i - 4));
#pragma unroll
        for (int j = 0; j < 8; j++) {
            int m = m0 + ((j < 4) ? (tx * 4 + j) : (64 + tx * 4 + j - 4));
            C[(size_t)n * M + m] = c[i][j] + bias[m];
        }
    }
}

// ---------------------------------------------------------------------------
// Periodic-causal attention. One warp per query (b,h,i).
// Valid keys: j = i mod p, i mod p + p, ..., i.  Online softmax, 4-key batches.
// Reads g_qkv, writes g_attn[(b*T+t)*D + h*HD + d].
// ---------------------------------------------------------------------------
__global__ __launch_bounds__(256)
void attn_kernel(const int* __restrict__ periods)
{
    const int bh   = blockIdx.y;
    const int b    = bh >> 3;
    const int h    = bh & 7;
    const int warp = threadIdx.x >> 5;
    const int lane = threadIdx.x & 31;
    const int i    = blockIdx.x * 8 + warp;

    int p = periods[bh];
    if (p < 1) p = 1;

    const float scale = 0.125f;  // 1/sqrt(64)
    const float* base = g_qkv + (size_t)b * T_ * QKV3;

    float2 q = ((const float2*)(base + (size_t)i * QKV3 + h * HD_))[lane];
    q.x *= scale; q.y *= scale;

    float  m = -1e30f, l = 0.f;
    float2 acc = make_float2(0.f, 0.f);

    const int j0 = i % p;
    const int nk = i / p + 1;
    int j = j0;

    const int nb4 = nk >> 2;
    for (int t = 0; t < nb4; t++) {
        float  s[4];
        float2 vv[4];
#pragma unroll
        for (int u = 0; u < 4; u++) {
            const float* kr = base + (size_t)(j + u * p) * QKV3 + D_ + h * HD_;
            float2 kk = ((const float2*)kr)[lane];
            vv[u]     = ((const float2*)(kr + D_))[lane];
            s[u] = q.x * kk.x + q.y * kk.y;
        }
#pragma unroll
        for (int u = 0; u < 4; u++)
#pragma unroll
            for (int o = 16; o > 0; o >>= 1)
                s[u] += __shfl_xor_sync(0xffffffffu, s[u], o);

        float mx = fmaxf(fmaxf(s[0], s[1]), fmaxf(s[2], s[3]));
        float nm = fmaxf(m, mx);
        float corr = __expf(m - nm);
        float p0 = __expf(s[0] - nm);
        float p1 = __expf(s[1] - nm);
        float p2 = __expf(s[2] - nm);
        float p3 = __expf(s[3] - nm);
        l = l * corr + (p0 + p1 + p2 + p3);
        acc.x = acc.x * corr + p0 * vv[0].x + p1 * vv[1].x + p2 * vv[2].x + p3 * vv[3].x;
        acc.y = acc.y * corr + p0 * vv[0].y + p1 * vv[1].y + p2 * vv[2].y + p3 * vv[3].y;
        m = nm;
        j += 4 * p;
    }
    for (; j <= i; j += p) {
        const float* kr = base + (size_t)j * QKV3 + D_ + h * HD_;
        float2 kk = ((const float2*)kr)[lane];
        float2 vv = ((const float2*)(kr + D_))[lane];
        float s = q.x * kk.x + q.y * kk.y;
#pragma unroll
        for (int o = 16; o > 0; o >>= 1)
            s += __shfl_xor_sync(0xffffffffu, s, o);
        float nm = fmaxf(m, s);
        float corr = __expf(m - nm);
        float pe = __expf(s - nm);
        l = l * corr + pe;
        acc.x = acc.x * corr + pe * vv.x;
        acc.y = acc.y * corr + pe * vv.y;
        m = nm;
    }

    float inv = 1.f / l;
    float2* orow = (float2*)(g_attn + ((size_t)(b * T_ + i)) * D_ + h * HD_);
    orow[lane] = make_float2(acc.x * inv, acc.y * inv);
}

// ---------------------------------------------------------------------------
extern "C" void kernel_launch(void* const* d_in, const int* in_sizes, int n_in,
                              void* d_out, int out_size)
{
    const float* x      = (const float*)d_in[0];   // (B,T,D)
    const int*   periods= (const int*)  d_in[1];   // (B,H)
    const float* w_qkv  = (const float*)d_in[2];   // (3D, D)
    const float* b_qkv  = (const float*)d_in[3];   // (3D)
    const float* w_out  = (const float*)d_in[4];   // (D, D)
    const float* b_out  = (const float*)d_in[5];   // (D)
    float*       out    = (float*)d_out;           // (B,T,D)

    float* qkv_ptr = nullptr;
    float* attn_ptr = nullptr;
    cudaGetSymbolAddress((void**)&qkv_ptr, g_qkv);
    cudaGetSymbolAddress((void**)&attn_ptr, g_attn);

    // 1) QKV projection: (4096 x 1536) = x (4096x512) @ w_qkv^T
    {
        dim3 grid(QKV3 / 128, NROW / 128);
        gemm_tn_bias<<<grid, 256>>>(x, w_qkv, b_qkv, qkv_ptr, NROW, QKV3, D_);
    }
    // 2) Periodic-causal attention
    {
        dim3 grid(T_ / 8, B_ * H_);
        attn_kernel<<<grid, 256>>>(periods);
    }
    // 3) Output projection: (4096 x 512) = attn (4096x512) @ w_out^T
    {
        dim3 grid(D_ / 128, NROW / 128);
        gemm_tn_bias<<<grid, 256>>>(attn_ptr, w_out, b_out, out, NROW, D_, D_);
    }
}

// round 2
// speedup vs baseline: 1.5474x; 1.5474x over previous
#include <cuda_runtime.h>
#include <math.h>
#include <stdint.h>

#define B_   2
#define T_   2048
#define D_   512
#define H_   8
#define HD_  64
#define QKV3 (3 * D_)   // 1536
#define NROW (B_ * T_)  // 4096

// Scratch (no cudaMalloc allowed)
__device__ float g_qkv[B_ * T_ * QKV3];   // (B,T, [q|k|v] each D)  ~25 MB
__device__ float g_attn[B_ * T_ * D_];    // (B,T,D) attention output ~8 MB

// ---------------------------------------------------------------------------
// TF32 tensor-core GEMM: C[n,m] = sum_k A[n,k]*W[m,k] + bias[m]
// A: (N,K) row-major, W: (M,K) row-major. N,M multiples of 128, K mult of 16.
// Block 128x128, 4 warps each computing 64x64, BK=16.
// Shared tiles stored k-major with row stride 136 floats (conflict-free frags).
// ---------------------------------------------------------------------------
#define SMS 136   // shared stride (floats); 136 % 32 == 8 -> conflict-free

__device__ __forceinline__ uint32_t f2tf32(float x) {
    uint32_t u;
    asm("cvt.rna.tf32.f32 %0, %1;" : "=r"(u) : "f"(x));
    return u;
}

__global__ __launch_bounds__(128)
void gemm_tf32_bias(const float* __restrict__ A, const float* __restrict__ W,
                    const float* __restrict__ bias, float* __restrict__ C,
                    int N, int M, int K)
{
    __shared__ uint32_t As[16 * SMS];
    __shared__ uint32_t Ws[16 * SMS];

    const int tid  = threadIdx.x;
    const int warp = tid >> 5;
    const int lane = tid & 31;
    const int g    = lane >> 2;   // 0..7
    const int t4   = lane & 3;    // 0..3

    const int n0 = blockIdx.y * 128;
    const int m0 = blockIdx.x * 128;
    const int r0 = (warp >> 1) * 64;   // warp row offset in tile
    const int c0 = (warp & 1) * 64;    // warp col offset in tile

    const float* Arow = A + (size_t)(n0 + tid) * K;
    const float* Wrow = W + (size_t)(m0 + tid) * K;

    float c[4][8][4];
#pragma unroll
    for (int mi = 0; mi < 4; mi++)
#pragma unroll
        for (int ni = 0; ni < 8; ni++)
#pragma unroll
            for (int q = 0; q < 4; q++) c[mi][ni][q] = 0.f;

    for (int k0 = 0; k0 < K; k0 += 16) {
        float4 av[4], wv[4];
#pragma unroll
        for (int j = 0; j < 4; j++) {
            av[j] = *(const float4*)(Arow + k0 + 4 * j);
            wv[j] = *(const float4*)(Wrow + k0 + 4 * j);
        }
        __syncthreads();
#pragma unroll
        for (int j = 0; j < 4; j++) {
            As[(4 * j + 0) * SMS + tid] = f2tf32(av[j].x);
            As[(4 * j + 1) * SMS + tid] = f2tf32(av[j].y);
            As[(4 * j + 2) * SMS + tid] = f2tf32(av[j].z);
            As[(4 * j + 3) * SMS + tid] = f2tf32(av[j].w);
            Ws[(4 * j + 0) * SMS + tid] = f2tf32(wv[j].x);
            Ws[(4 * j + 1) * SMS + tid] = f2tf32(wv[j].y);
            Ws[(4 * j + 2) * SMS + tid] = f2tf32(wv[j].z);
            Ws[(4 * j + 3) * SMS + tid] = f2tf32(wv[j].w);
        }
        __syncthreads();

#pragma unroll
        for (int kk = 0; kk < 16; kk += 8) {
            uint32_t b0[8], b1[8];
#pragma unroll
            for (int ni = 0; ni < 8; ni++) {
                b0[ni] = Ws[(kk + t4) * SMS     + c0 + ni * 8 + g];
                b1[ni] = Ws[(kk + 4 + t4) * SMS + c0 + ni * 8 + g];
            }
#pragma unroll
            for (int mi = 0; mi < 4; mi++) {
                uint32_t a0 = As[(kk + t4) * SMS     + r0 + mi * 16 + g];
                uint32_t a1 = As[(kk + t4) * SMS     + r0 + mi * 16 + g + 8];
                uint32_t a2 = As[(kk + 4 + t4) * SMS + r0 + mi * 16 + g];
                uint32_t a3 = As[(kk + 4 + t4) * SMS + r0 + mi * 16 + g + 8];
#pragma unroll
                for (int ni = 0; ni < 8; ni++) {
                    asm volatile(
                        "mma.sync.aligned.m16n8k8.row.col.f32.tf32.tf32.f32 "
                        "{%0,%1,%2,%3}, {%4,%5,%6,%7}, {%8,%9}, {%0,%1,%2,%3};"
                        : "+f"(c[mi][ni][0]), "+f"(c[mi][ni][1]),
                          "+f"(c[mi][ni][2]), "+f"(c[mi][ni][3])
                        : "r"(a0), "r"(a1), "r"(a2), "r"(a3),
                          "r"(b0[ni]), "r"(b1[ni]));
                }
            }
        }
    }

    // Epilogue: c0,c1 -> (row g, cols 2*t4, 2*t4+1); c2,c3 -> row g+8
#pragma unroll
    for (int mi = 0; mi < 4; mi++) {
        int row_a = n0 + r0 + mi * 16 + g;
        int row_b = row_a + 8;
#pragma unroll
        for (int ni = 0; ni < 8; ni++) {
            int col = m0 + c0 + ni * 8 + 2 * t4;
            float bx = bias[col], by = bias[col + 1];
            *(float2*)(C + (size_t)row_a * M + col) =
                make_float2(c[mi][ni][0] + bx, c[mi][ni][1] + by);
            *(float2*)(C + (size_t)row_b * M + col) =
                make_float2(c[mi][ni][2] + bx, c[mi][ni][3] + by);
        }
    }
}

// ---------------------------------------------------------------------------
// Periodic-causal attention. One warp per query (b,h,i).
// Valid keys: j = i mod p, i mod p + p, ..., i.  Online softmax, 4-key batches.
// ---------------------------------------------------------------------------
__global__ __launch_bounds__(256)
void attn_kernel(const int* __restrict__ periods)
{
    const int bh   = blockIdx.y;
    const int b    = bh >> 3;
    const int h    = bh & 7;
    const int warp = threadIdx.x >> 5;
    const int lane = threadIdx.x & 31;
    const int i    = blockIdx.x * 8 + warp;

    int p = periods[bh];
    if (p < 1) p = 1;

    const float scale = 0.125f;  // 1/sqrt(64)
    const float* base = g_qkv + (size_t)b * T_ * QKV3;

    float2 q = ((const float2*)(base + (size_t)i * QKV3 + h * HD_))[lane];
    q.x *= scale; q.y *= scale;

    float  m = -1e30f, l = 0.f;
    float2 acc = make_float2(0.f, 0.f);

    const int j0 = i % p;
    const int nk = i / p + 1;
    int j = j0;

    const int nb4 = nk >> 2;
    for (int t = 0; t < nb4; t++) {
        float  s[4];
        float2 vv[4];
#pragma unroll
        for (int u = 0; u < 4; u++) {
            const float* kr = base + (size_t)(j + u * p) * QKV3 + D_ + h * HD_;
            float2 kk = ((const float2*)kr)[lane];
            vv[u]     = ((const float2*)(kr + D_))[lane];
            s[u] = q.x * kk.x + q.y * kk.y;
        }
#pragma unroll
        for (int u = 0; u < 4; u++)
#pragma unroll
            for (int o = 16; o > 0; o >>= 1)
                s[u] += __shfl_xor_sync(0xffffffffu, s[u], o);

        float mx = fmaxf(fmaxf(s[0], s[1]), fmaxf(s[2], s[3]));
        float nm = fmaxf(m, mx);
        float corr = __expf(m - nm);
        float p0 = __expf(s[0] - nm);
        float p1 = __expf(s[1] - nm);
        float p2 = __expf(s[2] - nm);
        float p3 = __expf(s[3] - nm);
        l = l * corr + (p0 + p1 + p2 + p3);
        acc.x = acc.x * corr + p0 * vv[0].x + p1 * vv[1].x + p2 * vv[2].x + p3 * vv[3].x;
        acc.y = acc.y * corr + p0 * vv[0].y + p1 * vv[1].y + p2 * vv[2].y + p3 * vv[3].y;
        m = nm;
        j += 4 * p;
    }
    for (; j <= i; j += p) {
        const float* kr = base + (size_t)j * QKV3 + D_ + h * HD_;
        float2 kk = ((const float2*)kr)[lane];
        float2 vv = ((const float2*)(kr + D_))[lane];
        float s = q.x * kk.x + q.y * kk.y;
#pragma unroll
        for (int o = 16; o > 0; o >>= 1)
            s += __shfl_xor_sync(0xffffffffu, s, o);
        float nm = fmaxf(m, s);
        float corr = __expf(m - nm);
        float pe = __expf(s - nm);
        l = l * corr + pe;
        acc.x = acc.x * corr + pe * vv.x;
        acc.y = acc.y * corr + pe * vv.y;
        m = nm;
    }

    float inv = 1.f / l;
    float2* orow = (float2*)(g_attn + ((size_t)(b * T_ + i)) * D_ + h * HD_);
    orow[lane] = make_float2(acc.x * inv, acc.y * inv);
}

// ---------------------------------------------------------------------------
extern "C" void kernel_launch(void* const* d_in, const int* in_sizes, int n_in,
                              void* d_out, int out_size)
{
    const float* x      = (const float*)d_in[0];   // (B,T,D)
    const int*   periods= (const int*)  d_in[1];   // (B,H)
    const float* w_qkv  = (const float*)d_in[2];   // (3D, D)
    const float* b_qkv  = (const float*)d_in[3];   // (3D)
    const float* w_out  = (const float*)d_in[4];   // (D, D)
    const float* b_out  = (const float*)d_in[5];   // (D)
    float*       out    = (float*)d_out;           // (B,T,D)

    float* qkv_ptr = nullptr;
    float* attn_ptr = nullptr;
    cudaGetSymbolAddress((void**)&qkv_ptr, g_qkv);
    cudaGetSymbolAddress((void**)&attn_ptr, g_attn);

    // 1) QKV projection: (4096 x 1536) = x (4096x512) @ w_qkv^T
    {
        dim3 grid(QKV3 / 128, NROW / 128);
        gemm_tf32_bias<<<grid, 128>>>(x, w_qkv, b_qkv, qkv_ptr, NROW, QKV3, D_);
    }
    // 2) Periodic-causal attention
    {
        dim3 grid(T_ / 8, B_ * H_);
        attn_kernel<<<grid, 256>>>(periods);
    }
    // 3) Output projection: (4096 x 512) = attn (4096x512) @ w_out^T
    {
        dim3 grid(D_ / 128, NROW / 128);
        gemm_tf32_bias<<<grid, 128>>>(attn_ptr, w_out, b_out, out, NROW, D_, D_);
    }
}

// round 3
// speedup vs baseline: 1.9866x; 1.2838x over previous
#include <cuda_runtime.h>
#include <math.h>
#include <stdint.h>

#define B_   2
#define T_   2048
#define D_   512
#define H_   8
#define HD_  64
#define QKV3 (3 * D_)   // 1536
#define NROW (B_ * T_)  // 4096

// Scratch (no cudaMalloc allowed)
__device__ float g_qkv[B_ * T_ * QKV3];   // (B,T, [q|k|v] each D)
__device__ float g_attn[B_ * T_ * D_];    // (B,T,D)

// ---------------------------------------------------------------------------
// TF32 tensor-core GEMM, double-buffered: C[n,m] = sum_k A[n,k]*W[m,k] + bias
// Block 128x128, BK=16, 256 threads (8 warps, 64x32 warp tiles).
// ---------------------------------------------------------------------------
#define SMS 136   // shared k-major row stride (floats); 136 % 32 == 8

__device__ __forceinline__ uint32_t f2tf32(float x) {
    uint32_t u;
    asm("cvt.rna.tf32.f32 %0, %1;" : "=r"(u) : "f"(x));
    return u;
}

__global__ __launch_bounds__(256)
void gemm_tf32_pipe(const float* __restrict__ A, const float* __restrict__ W,
                    const float* __restrict__ bias, float* __restrict__ C,
                    int N, int M, int K)
{
    __shared__ uint32_t As[2][16 * SMS];
    __shared__ uint32_t Ws[2][16 * SMS];

    const int tid  = threadIdx.x;
    const int warp = tid >> 5;
    const int lane = tid & 31;
    const int g    = lane >> 2;   // 0..7
    const int t4   = lane & 3;    // 0..3

    const int n0 = blockIdx.y * 128;
    const int m0 = blockIdx.x * 128;
    const int r0 = (warp >> 2) * 64;   // 0 / 64
    const int c0 = (warp & 3) * 32;    // 0,32,64,96

    const int lrow = tid >> 1;         // 0..127
    const int lk   = (tid & 1) * 8;    // 0 / 8
    const float* Arow = A + (size_t)(n0 + lrow) * K + lk;
    const float* Wrow = W + (size_t)(m0 + lrow) * K + lk;

    float c[4][4][4];
#pragma unroll
    for (int mi = 0; mi < 4; mi++)
#pragma unroll
        for (int ni = 0; ni < 4; ni++)
#pragma unroll
            for (int q = 0; q < 4; q++) c[mi][ni][q] = 0.f;

    float4 av0, av1, wv0, wv1;
    av0 = *(const float4*)(Arow);
    av1 = *(const float4*)(Arow + 4);
    wv0 = *(const float4*)(Wrow);
    wv1 = *(const float4*)(Wrow + 4);
    {
        uint32_t* as = &As[0][lk * SMS + lrow];
        as[0*SMS]=f2tf32(av0.x); as[1*SMS]=f2tf32(av0.y);
        as[2*SMS]=f2tf32(av0.z); as[3*SMS]=f2tf32(av0.w);
        as[4*SMS]=f2tf32(av1.x); as[5*SMS]=f2tf32(av1.y);
        as[6*SMS]=f2tf32(av1.z); as[7*SMS]=f2tf32(av1.w);
        uint32_t* ws = &Ws[0][lk * SMS + lrow];
        ws[0*SMS]=f2tf32(wv0.x); ws[1*SMS]=f2tf32(wv0.y);
        ws[2*SMS]=f2tf32(wv0.z); ws[3*SMS]=f2tf32(wv0.w);
        ws[4*SMS]=f2tf32(wv1.x); ws[5*SMS]=f2tf32(wv1.y);
        ws[6*SMS]=f2tf32(wv1.z); ws[7*SMS]=f2tf32(wv1.w);
    }
    __syncthreads();

    const int NT = K / 16;
    for (int it = 0; it < NT; it++) {
        if (it + 1 < NT) {   // prefetch next tile into registers (overlaps MMA)
            const float* Ap = Arow + (it + 1) * 16;
            const float* Wp = Wrow + (it + 1) * 16;
            av0 = *(const float4*)(Ap);
            av1 = *(const float4*)(Ap + 4);
            wv0 = *(const float4*)(Wp);
            wv1 = *(const float4*)(Wp + 4);
        }
        const uint32_t* asb = As[it & 1];
        const uint32_t* wsb = Ws[it & 1];
#pragma unroll
        for (int kk = 0; kk < 16; kk += 8) {
            uint32_t b0[4], b1[4];
#pragma unroll
            for (int ni = 0; ni < 4; ni++) {
                b0[ni] = wsb[(kk + t4) * SMS     + c0 + ni * 8 + g];
                b1[ni] = wsb[(kk + 4 + t4) * SMS + c0 + ni * 8 + g];
            }
#pragma unroll
            for (int mi = 0; mi < 4; mi++) {
                uint32_t a0 = asb[(kk + t4) * SMS     + r0 + mi * 16 + g];
                uint32_t a1 = asb[(kk + t4) * SMS     + r0 + mi * 16 + g + 8];
                uint32_t a2 = asb[(kk + 4 + t4) * SMS + r0 + mi * 16 + g];
                uint32_t a3 = asb[(kk + 4 + t4) * SMS + r0 + mi * 16 + g + 8];
#pragma unroll
                for (int ni = 0; ni < 4; ni++) {
                    asm volatile(
                        "mma.sync.aligned.m16n8k8.row.col.f32.tf32.tf32.f32 "
                        "{%0,%1,%2,%3}, {%4,%5,%6,%7}, {%8,%9}, {%0,%1,%2,%3};"
                        : "+f"(c[mi][ni][0]), "+f"(c[mi][ni][1]),
                          "+f"(c[mi][ni][2]), "+f"(c[mi][ni][3])
                        : "r"(a0), "r"(a1), "r"(a2), "r"(a3),
                          "r"(b0[ni]), "r"(b1[ni]));
                }
            }
        }
        if (it + 1 < NT) {
            __syncthreads();   // all warps done reading buf[(it+1)&1]
            uint32_t* as = &As[(it + 1) & 1][lk * SMS + lrow];
            as[0*SMS]=f2tf32(av0.x); as[1*SMS]=f2tf32(av0.y);
            as[2*SMS]=f2tf32(av0.z); as[3*SMS]=f2tf32(av0.w);
            as[4*SMS]=f2tf32(av1.x); as[5*SMS]=f2tf32(av1.y);
            as[6*SMS]=f2tf32(av1.z); as[7*SMS]=f2tf32(av1.w);
            uint32_t* ws = &Ws[(it + 1) & 1][lk * SMS + lrow];
            ws[0*SMS]=f2tf32(wv0.x); ws[1*SMS]=f2tf32(wv0.y);
            ws[2*SMS]=f2tf32(wv0.z); ws[3*SMS]=f2tf32(wv0.w);
            ws[4*SMS]=f2tf32(wv1.x); ws[5*SMS]=f2tf32(wv1.y);
            ws[6*SMS]=f2tf32(wv1.z); ws[7*SMS]=f2tf32(wv1.w);
            __syncthreads();
        }
    }

#pragma unroll
    for (int mi = 0; mi < 4; mi++) {
        int row_a = n0 + r0 + mi * 16 + g;
        int row_b = row_a + 8;
#pragma unroll
        for (int ni = 0; ni < 4; ni++) {
            int col = m0 + c0 + ni * 8 + 2 * t4;
            float bx = bias[col], by = bias[col + 1];
            *(float2*)(C + (size_t)row_a * M + col) =
                make_float2(c[mi][ni][0] + bx, c[mi][ni][1] + by);
            *(float2*)(C + (size_t)row_b * M + col) =
                make_float2(c[mi][ni][2] + bx, c[mi][ni][3] + by);
        }
    }
}

// ---------------------------------------------------------------------------
// Residue-class attention.
// Queries with i % p == r share key set {r, r+p, ...}. Block = (bh, r, 8-query
// tile of class positions). Keys staged into smem in 64-key chunks; 2 warps
// per query (even/odd 32-key chunks), lane = key, combine halves at the end.
// ---------------------------------------------------------------------------
#define AQ 8
__global__ __launch_bounds__(512)
void attn_class_kernel(const int* __restrict__ periods)
{
    const int bh = blockIdx.y;
    const int b  = bh >> 3;
    const int h  = bh & 7;
    int p = periods[bh];
    if (p < 1) p = 1;

    const int x    = blockIdx.x;
    const int r    = x % p;
    const int tile = x / p;
    const int c0   = tile * AQ;
    if (r + c0 * p > T_ - 1) return;     // uniform over block

    const int tid  = threadIdx.x;
    const int warp = tid >> 5;
    const int lane = tid & 31;

    const int L    = (T_ - 1 - r) / p + 1;          // class length
    const int cmax = min(c0 + AQ - 1, L - 1);
    const int nch  = cmax / 32 + 1;                 // 32-key chunks

    __shared__ float Ks[64 * 65];
    __shared__ float Vs[64 * 65];
    __shared__ float Qs[AQ][64];
    __shared__ float Cmb[AQ][66];

    const float* base = g_qkv + (size_t)b * T_ * QKV3;

    // stage scaled Q
    {
        int qi = tid >> 6, d = tid & 63;       // 512 threads = 8*64
        int cq = c0 + qi;
        float qv = 0.f;
        if (cq <= cmax) {
            int iq = r + cq * p;
            qv = base[(size_t)iq * QKV3 + h * HD_ + d] * 0.125f;
        }
        Qs[qi][d] = qv;
    }

    const int q    = warp & 7;
    const int half = warp >> 3;      // 0: even chunks, 1: odd chunks
    const int cq   = c0 + q;
    const bool qvalid = (cq <= cmax);

    float m_run = -1e30f, l_run = 0.f;
    float accA = 0.f, accB = 0.f;    // dims lane, lane+32

    const int niter = (nch + 1) >> 1;
    for (int t = 0; t < niter; t++) {
        __syncthreads();
        {   // stage 64 keys: m in [64t, 64t+64)
            int row   = tid >> 3;
            int cb    = (tid & 7) * 8;
            int mg    = t * 64 + row;
            if (mg <= cmax) {
                int ik = r + mg * p;
                const float* kr = base + (size_t)ik * QKV3 + D_ + h * HD_ + cb;
                float4 k0 = *(const float4*)(kr);
                float4 k1 = *(const float4*)(kr + 4);
                float4 v0 = *(const float4*)(kr + D_);
                float4 v1 = *(const float4*)(kr + D_ + 4);
                float* kd = &Ks[row * 65 + cb];
                kd[0]=k0.x; kd[1]=k0.y; kd[2]=k0.z; kd[3]=k0.w;
                kd[4]=k1.x; kd[5]=k1.y; kd[6]=k1.z; kd[7]=k1.w;
                float* vd = &Vs[row * 65 + cb];
                vd[0]=v0.x; vd[1]=v0.y; vd[2]=v0.z; vd[3]=v0.w;
                vd[4]=v1.x; vd[5]=v1.y; vd[6]=v1.z; vd[7]=v1.w;
            }
        }
        __syncthreads();

        const int ch = 2 * t + half;
        const int m0 = ch * 32;
        if (qvalid && ch < nch && m0 <= cq) {
            const int rb = half * 32;
            float s = -1e30f;
            if (m0 + lane <= cq) {
                const float* kr2 = &Ks[(rb + lane) * 65];
                const float* qp  = Qs[q];
                float d0 = 0.f, d1 = 0.f, d2 = 0.f, d3 = 0.f;
#pragma unroll
                for (int d = 0; d < 64; d += 4) {
                    d0 = fmaf(qp[d],     kr2[d],     d0);
                    d1 = fmaf(qp[d + 1], kr2[d + 1], d1);
                    d2 = fmaf(qp[d + 2], kr2[d + 2], d2);
                    d3 = fmaf(qp[d + 3], kr2[d + 3], d3);
                }
                s = (d0 + d1) + (d2 + d3);
            }
            float cm = s;
#pragma unroll
            for (int o = 16; o > 0; o >>= 1)
                cm = fmaxf(cm, __shfl_xor_sync(0xffffffffu, cm, o));
            float nm   = fmaxf(m_run, cm);
            float corr = __expf(m_run - nm);
            float pe   = __expf(s - nm);     // masked lanes -> 0
            float cs = pe;
#pragma unroll
            for (int o = 16; o > 0; o >>= 1)
                cs += __shfl_xor_sync(0xffffffffu, cs, o);
            l_run = l_run * corr + cs;

            float a0 = 0.f, a1 = 0.f, b0 = 0.f, b1 = 0.f;
#pragma unroll 4
            for (int j = 0; j < 32; j += 2) {
                float pj0 = __shfl_sync(0xffffffffu, pe, j);
                float pj1 = __shfl_sync(0xffffffffu, pe, j + 1);
                const float* v0 = &Vs[(rb + j) * 65];
                const float* v1 = &Vs[(rb + j + 1) * 65];
                a0 = fmaf(pj0, v0[lane],      a0);
                b0 = fmaf(pj0, v0[32 + lane], b0);
                a1 = fmaf(pj1, v1[lane],      a1);
                b1 = fmaf(pj1, v1[32 + lane], b1);
            }
            accA = fmaf(accA, corr, a0 + a1);
            accB = fmaf(accB, corr, b0 + b1);
            m_run = nm;
        }
    }

    // combine even/odd halves
    __syncthreads();
    if (half == 1 && qvalid) {
        if (lane == 0) { Cmb[q][0] = m_run; Cmb[q][1] = l_run; }
        Cmb[q][2 + lane]      = accA;
        Cmb[q][2 + 32 + lane] = accB;
    }
    __syncthreads();
    if (half == 0 && qvalid) {
        float mb = Cmb[q][0], lb = Cmb[q][1];
        float nm = fmaxf(m_run, mb);
        float ca = __expf(m_run - nm), cb = __expf(mb - nm);
        float l  = l_run * ca + lb * cb;
        float oA = accA * ca + Cmb[q][2 + lane] * cb;
        float oB = accB * ca + Cmb[q][2 + 32 + lane] * cb;
        float inv = 1.f / l;
        int iq = r + cq * p;
        float* orow = g_attn + (size_t)(b * T_ + iq) * D_ + h * HD_;
        orow[lane]      = oA * inv;
        orow[lane + 32] = oB * inv;
    }
}

// ---------------------------------------------------------------------------
extern "C" void kernel_launch(void* const* d_in, const int* in_sizes, int n_in,
                              void* d_out, int out_size)
{
    const float* x      = (const float*)d_in[0];
    const int*   periods= (const int*)  d_in[1];
    const float* w_qkv  = (const float*)d_in[2];
    const float* b_qkv  = (const float*)d_in[3];
    const float* w_out  = (const float*)d_in[4];
    const float* b_out  = (const float*)d_in[5];
    float*       out    = (float*)d_out;

    float* qkv_ptr = nullptr;
    float* attn_ptr = nullptr;
    cudaGetSymbolAddress((void**)&qkv_ptr, g_qkv);
    cudaGetSymbolAddress((void**)&attn_ptr, g_attn);

    {   // QKV projection
        dim3 grid(QKV3 / 128, NROW / 128);
        gemm_tf32_pipe<<<grid, 256>>>(x, w_qkv, b_qkv, qkv_ptr, NROW, QKV3, D_);
    }
    {   // periodic-causal attention (residue classes)
        dim3 grid(320, B_ * H_);
        attn_class_kernel<<<grid, 512>>>(periods);
    }
    {   // output projection
        dim3 grid(D_ / 128, NROW / 128);
        gemm_tf32_pipe<<<grid, 256>>>(attn_ptr, w_out, b_out, out, NROW, D_, D_);
    }
}